// round 4
// baseline (speedup 1.0000x reference)
#include <cuda_runtime.h>

// crossMSEloss: B=4, S=256, P=64, D=63
// out[b,s] = sum_p conf[p] * min_q ||pred_p - tgt_q||
//          + sum_q min_p ( ||pred_p - tgt_q|| / conf[p] )
//
// GEMM-form (norm trick), f32x2 packed FMA mainloop, 2p x 8q register tiles,
// granule-swizzled transposed targets for conflict-free 16B b-loads,
// shuffle-based min reductions, 5 blocks/SM.

#define NP 64
#define SP_S 68     // preds stride (272B, 16B-multiple, conflict-free f4 rows)
#define STT_S 68    // transposed targets stride
#define SH_S 65     // half-staging stride
#define CM_S 68

typedef unsigned long long u64;

__device__ __forceinline__ u64 pack2(float x) {
    u64 r; asm("mov.b64 %0, {%1, %1};" : "=l"(r) : "f"(x)); return r;
}
__device__ __forceinline__ void ffma2(u64& d, u64 a, u64 b) {
    asm("fma.rn.f32x2 %0, %1, %2, %0;" : "+l"(d) : "l"(a), "l"(b));
}
__device__ __forceinline__ void unpack2(float& lo, float& hi, u64 v) {
    asm("mov.b64 {%0, %1}, %2;" : "=f"(lo), "=f"(hi) : "l"(v));
}

// Physical float offset of logical column q within an st_t row.
// Quad gl=q>>2 goes to granule (gl>>1) | ((gl&1)<<3): even quads occupy the
// low 128B half, odd quads the high half. Thread tx then reads logical
// q=8tx..8tx+3 at float 4*tx (granule tx) and q=8tx+4..8tx+7 at float 32+4*tx.
__device__ __forceinline__ int physq(int q) {
    int gl = q >> 2;
    int gp = (gl >> 1) | ((gl & 1) << 3);
    return gp * 4 + (q & 3);
}

__global__ __launch_bounds__(256, 5)
void cross_mse_loss_kernel(const float* __restrict__ inp,
                           const float* __restrict__ tgt,
                           float* __restrict__ out)
{
    __shared__ __align__(16) float sp[NP * SP_S];      // preds [p][d], d=63 -> 0
    __shared__ __align__(16) float st_t[NP * STT_S];   // targets [d][physq]
    __shared__ __align__(16) float sh[32 * SH_S];      // half staging; aliases cm
    __shared__ float rm[NP];                           // final row mins (d^2)
    __shared__ float conf[NP];
    __shared__ float cinv2[NP];
    __shared__ float pn[NP];
    __shared__ float qn[NP];
    __shared__ float red[128];

    float* cm = sh;   // [8 warps][CM_S] col-min partials (sh dead by then)

    const int bs  = blockIdx.x;
    const int tid = threadIdx.x;

    const float* ip = inp + (size_t)bs * (NP * 64);
    const float* tp = tgt + (size_t)bs * (NP * 63);

    // ---- Preds (+conf) via float4; zero-pad d=63 ----
    const float4* ip4 = (const float4*)ip;
    #pragma unroll
    for (int r = 0; r < 4; r++) {
        int idx = tid + r * 256;
        float4 v = ip4[idx];
        int p  = idx >> 4;
        int d4 = (idx & 15) << 2;
        float* row = sp + p * SP_S + d4;
        if (d4 == 60) {
            row[0] = v.x; row[1] = v.y; row[2] = v.z; row[3] = 0.0f;
            conf[p] = v.w;
            float ci = 1.0f / v.w;
            cinv2[p] = ci * ci;
        } else {
            row[0] = v.x; row[1] = v.y; row[2] = v.z; row[3] = v.w;
        }
    }

    // ---- Targets: two half-tiles (32 q-rows each): stage -> transpose ----
    #pragma unroll
    for (int half = 0; half < 2; half++) {
        const float* tph = tp + half * 32 * 63;
        #pragma unroll
        for (int k = 0; k < 8; k++) {
            int i = tid + k * 256;
            if (i < 32 * 63) {
                int q = i / 63;
                int d = i - q * 63;
                sh[q * SH_S + d] = tph[i];
            }
        }
        if (tid < 32) sh[tid * SH_S + 63] = 0.0f;
        __syncthreads();
        // transpose: 2048 elems, lanes sweep q (conflict-free both sides)
        #pragma unroll
        for (int k = 0; k < 8; k++) {
            int i = tid + k * 256;
            int d  = i >> 5;
            int q32 = i & 31;
            st_t[d * STT_S + physq(half * 32 + q32)] = sh[q32 * SH_S + d];
        }
        __syncthreads();
    }

    // ---- Norms: threads 0..63 -> pn (float4 rows), 64..127 -> qn (st_t cols) ----
    if (tid < NP) {
        const float4* ap = (const float4*)(sp + tid * SP_S);
        float s = 0.0f;
        #pragma unroll
        for (int k = 0; k < 16; k++) {
            float4 a = ap[k];
            s = fmaf(a.x, a.x, s); s = fmaf(a.y, a.y, s);
            s = fmaf(a.z, a.z, s); s = fmaf(a.w, a.w, s);
        }
        pn[tid] = s;
    } else if (tid < 2 * NP) {
        int q = tid - NP;
        int po = physq(q);
        float s = 0.0f;
        #pragma unroll 8
        for (int d = 0; d < 64; d++) {
            float b = st_t[d * STT_S + po];
            s = fmaf(b, b, s);
        }
        qn[q] = s;
    }
    __syncthreads();

    // ---- Mainloop: 2p x 8q tiles, f32x2 FMA ----
    const int tx = tid & 7;          // q0 = 8*tx
    const int ty = tid >> 3;         // p0 = 2*ty
    const int q0 = tx * 8;
    const int p0 = ty * 2;

    u64 acc[2][4];
    #pragma unroll
    for (int i = 0; i < 2; i++)
        #pragma unroll
        for (int j = 0; j < 4; j++) acc[i][j] = 0ull;

    const float* brow  = st_t + tx * 4;    // bA at d*STT_S, bB at +32
    const float* arow0 = sp + p0 * SP_S;
    const float* arow1 = arow0 + SP_S;

    #pragma unroll 8
    for (int dc = 0; dc < 64; dc += 4) {
        float4 av0 = *(const float4*)(arow0 + dc);
        float4 av1 = *(const float4*)(arow1 + dc);
        float a0[4] = {av0.x, av0.y, av0.z, av0.w};
        float a1[4] = {av1.x, av1.y, av1.z, av1.w};
        #pragma unroll
        for (int d = 0; d < 4; d++) {
            const float* bp = brow + (dc + d) * STT_S;
            ulonglong2 bA = *(const ulonglong2*)(bp);
            ulonglong2 bB = *(const ulonglong2*)(bp + 32);
            u64 pa0 = pack2(a0[d]);
            ffma2(acc[0][0], pa0, bA.x); ffma2(acc[0][1], pa0, bA.y);
            ffma2(acc[0][2], pa0, bB.x); ffma2(acc[0][3], pa0, bB.y);
            u64 pa1 = pack2(a1[d]);
            ffma2(acc[1][0], pa1, bA.x); ffma2(acc[1][1], pa1, bA.y);
            ffma2(acc[1][2], pa1, bB.x); ffma2(acc[1][3], pa1, bB.y);
        }
    }

    // ---- Epilogue: d^2, per-thread mins ----
    float pnr0 = pn[p0], pnr1 = pn[p0 + 1];
    float ci0  = cinv2[p0], ci1 = cinv2[p0 + 1];

    float rmin0 = 1e30f, rmin1 = 1e30f;
    float cmin[8];
    #pragma unroll
    for (int j = 0; j < 8; j++) cmin[j] = 1e30f;

    #pragma unroll
    for (int i = 0; i < 2; i++) {
        float dot[8];
        unpack2(dot[0], dot[1], acc[i][0]);
        unpack2(dot[2], dot[3], acc[i][1]);
        unpack2(dot[4], dot[5], acc[i][2]);
        unpack2(dot[6], dot[7], acc[i][3]);
        float pnr = i ? pnr1 : pnr0;
        float ci  = i ? ci1  : ci0;
        float rmn = 1e30f;
        #pragma unroll
        for (int j = 0; j < 8; j++) {
            float d2 = fmaxf(fmaf(-2.0f, dot[j], pnr + qn[q0 + j]), 0.0f);
            rmn = fminf(rmn, d2);
            cmin[j] = fminf(cmin[j], d2 * ci);
        }
        if (i) rmin1 = rmn; else rmin0 = rmn;
    }

    // row-min: q fully covered within warp by tx lanes (bits 0..2)
    #pragma unroll
    for (int m = 1; m < 8; m <<= 1) {
        rmin0 = fminf(rmin0, __shfl_xor_sync(0xFFFFFFFFu, rmin0, m));
        rmin1 = fminf(rmin1, __shfl_xor_sync(0xFFFFFFFFu, rmin1, m));
    }
    // col-min: combine 4 ty-groups within warp (bits 3,4)
    #pragma unroll
    for (int j = 0; j < 8; j++) {
        cmin[j] = fminf(cmin[j], __shfl_xor_sync(0xFFFFFFFFu, cmin[j], 8));
        cmin[j] = fminf(cmin[j], __shfl_xor_sync(0xFFFFFFFFu, cmin[j], 16));
    }
    __syncthreads();   // sh staging dead -> cm alias safe
    if (tx == 0) { rm[p0] = rmin0; rm[p0 + 1] = rmin1; }
    if ((tid & 24) == 0) {   // lane>>3 == 0: one lane per tx per warp
        const int w = tid >> 5;
        #pragma unroll
        for (int j = 0; j < 8; j++) cm[w * CM_S + q0 + j] = cmin[j];
    }
    __syncthreads();

    // ---- Final: 128 sqrts + block sum ----
    float val = 0.0f;
    if (tid < NP) {
        val = conf[tid] * sqrtf(rm[tid]);
    } else if (tid < 2 * NP) {
        int q = tid - NP;
        float m = cm[q];
        #pragma unroll
        for (int w = 1; w < 8; w++) m = fminf(m, cm[w * CM_S + q]);
        val = sqrtf(m);
    }

    if (tid < 128) red[tid] = val;
    __syncthreads();
    if (tid < 64) red[tid] += red[tid + 64];
    __syncthreads();
    if (tid < 32) {
        float s = red[tid] + red[tid + 32];
        #pragma unroll
        for (int off = 16; off > 0; off >>= 1)
            s += __shfl_down_sync(0xFFFFFFFFu, s, off);
        if (tid == 0) out[bs] = s;
    }
}

extern "C" void kernel_launch(void* const* d_in, const int* in_sizes, int n_in,
                              void* d_out, int out_size)
{
    const float* inp = (const float*)d_in[0];
    const float* tgt = (const float*)d_in[1];
    float* out = (float*)d_out;
    cross_mse_loss_kernel<<<1024, 256>>>(inp, tgt, out);
}

// round 5
// speedup vs baseline: 1.0655x; 1.0655x over previous
#include <cuda_runtime.h>

// crossMSEloss: B=4, S=256, P=64, D=63
// out[b,s] = sum_p conf[p] * min_q ||pred_p - tgt_q||
//          + sum_q min_p ( ||pred_p - tgt_q|| / conf[p] )
//
// GEMM-form (norm trick). 4p x 4q register tiles, f32x2 FMAs packed along d
// (both operands d-contiguous -> no transpose, no register packing).
// Targets stored with per-row granule rotation for conflict-free lane-strided
// row reads. Mins on squared distances; 128 sqrts/block.

#define NP 64
#define SP_S 68     // preds stride: 272B; 2 distinct warp rows -> conflict-free
#define CM_S 68

typedef unsigned long long u64;

__device__ __forceinline__ void ffma2(u64& d, u64 a, u64 b) {
    asm("fma.rn.f32x2 %0, %1, %2, %0;" : "+l"(d) : "l"(a), "l"(b));
}
__device__ __forceinline__ void unpack2(float& lo, float& hi, u64 v) {
    asm("mov.b64 {%0, %1}, %2;" : "=f"(lo), "=f"(hi) : "l"(v));
}

__global__ __launch_bounds__(256, 4)
void cross_mse_loss_kernel(const float* __restrict__ inp,
                           const float* __restrict__ tgt,
                           float* __restrict__ out)
{
    __shared__ __align__(16) float sp[NP * SP_S];   // preds [p][d], d=63 -> 0
    __shared__ __align__(16) float st[NP * 64];     // targets, granule-rotated rows
    __shared__ float cm[8 * CM_S];                  // per-warp col-min partials
    __shared__ float rm[NP];
    __shared__ float conf[NP];
    __shared__ float cinv2[NP];
    __shared__ float pn[NP];
    __shared__ float qn[NP];
    __shared__ float red[128];

    const int bs  = blockIdx.x;
    const int tid = threadIdx.x;
    const int lane15 = tid & 15;

    const float* ip = inp + (size_t)bs * (NP * 64);
    const float* tp = tgt + (size_t)bs * (NP * 63);

    // ---- Zero st (rotation scatter needs a clean d=63 pad) ----
    {
        float4 z = make_float4(0.f, 0.f, 0.f, 0.f);
        float4* st4 = (float4*)st;
        #pragma unroll
        for (int r = 0; r < 4; r++) st4[tid + r * 256] = z;
    }

    // ---- Preds (+conf) via float4; pn computed inline via 16-lane shuffles ----
    const float4* ip4 = (const float4*)ip;
    #pragma unroll
    for (int r = 0; r < 4; r++) {
        int idx = tid + r * 256;          // p = idx>>4, d4 = (idx&15)*4
        float4 v = ip4[idx];
        int p  = idx >> 4;
        int d4 = lane15 << 2;
        float* row = sp + p * SP_S + d4;
        float s;
        if (d4 == 60) {
            row[0] = v.x; row[1] = v.y; row[2] = v.z; row[3] = 0.0f;
            conf[p] = v.w;
            float ci = 1.0f / v.w;
            cinv2[p] = ci * ci;
            s = fmaf(v.x, v.x, fmaf(v.y, v.y, v.z * v.z));
        } else {
            row[0] = v.x; row[1] = v.y; row[2] = v.z; row[3] = v.w;
            s = fmaf(v.x, v.x, fmaf(v.y, v.y, fmaf(v.z, v.z, v.w * v.w)));
        }
        // reduce over the 16 lanes holding pieces of p (xor <16 stays in group)
        #pragma unroll
        for (int m = 1; m < 16; m <<= 1)
            s += __shfl_xor_sync(0xFFFFFFFFu, s, m);
        if (lane15 == 0) pn[p] = s;
    }

    __syncthreads();   // st zeroed before scatter (different threads' granules)

    // ---- Targets via float4 gmem loads, scatter into rotated layout ----
    // element (q,d) -> st[q*64 + 4*(((d>>2)+(q>>2))&15) + (d&3)]
    const float4* tp4 = (const float4*)tp;   // 1008 float4 = 4032 floats
    #pragma unroll
    for (int r = 0; r < 4; r++) {
        int idx = tid + r * 256;
        if (idx < 1008) {
            float4 v = tp4[idx];
            int e0 = idx << 2;
            float vv[4] = {v.x, v.y, v.z, v.w};
            #pragma unroll
            for (int c = 0; c < 4; c++) {
                int e = e0 + c;
                int q = e / 63;
                int d = e - q * 63;
                st[q * 64 + 4 * (((d >> 2) + (q >> 2)) & 15) + (d & 3)] = vv[c];
            }
        }
    }
    __syncthreads();

    // ---- qn: thread q scans its rotated row ----
    if (tid < NP) {
        const int q = tid;
        const float* rowq = st + q * 64;
        const int rot = q >> 2;
        float s = 0.0f;
        #pragma unroll
        for (int g = 0; g < 16; g++) {
            const float4 b = *(const float4*)(rowq + 4 * ((g + rot) & 15));
            s = fmaf(b.x, b.x, fmaf(b.y, b.y, fmaf(b.z, b.z, fmaf(b.w, b.w, s))));
        }
        qn[q] = s;
    }
    __syncthreads();

    // ---- Mainloop: 4p x 4q tiles, f32x2 packed along d ----
    const int tx = lane15;            // q0 = 4*tx
    const int ty = tid >> 4;          // p0 = 4*ty
    const int q0 = tx * 4;
    const int p0 = ty * 4;

    u64 acc[4][4];
    #pragma unroll
    for (int i = 0; i < 4; i++)
        #pragma unroll
        for (int j = 0; j < 4; j++) acc[i][j] = 0ull;

    const float* a0 = sp + p0 * SP_S;
    const float* b0 = st + q0 * 64;

    #pragma unroll 4
    for (int g = 0; g < 16; g++) {
        const int bofs = 4 * ((g + tx) & 15);   // rotated granule, rows q0..q0+3
        ulonglong2 b[4];
        #pragma unroll
        for (int j = 0; j < 4; j++)
            b[j] = *(const ulonglong2*)(b0 + j * 64 + bofs);
        #pragma unroll
        for (int i = 0; i < 4; i++) {
            ulonglong2 a = *(const ulonglong2*)(a0 + i * SP_S + 4 * g);
            #pragma unroll
            for (int j = 0; j < 4; j++) {
                ffma2(acc[i][j], a.x, b[j].x);
                ffma2(acc[i][j], a.y, b[j].y);
            }
        }
    }

    // ---- Epilogue: d^2, per-thread mins, shuffle reductions ----
    float pnr[4], ci2[4], qnr[4];
    #pragma unroll
    for (int i = 0; i < 4; i++) { pnr[i] = pn[p0 + i]; ci2[i] = cinv2[p0 + i]; }
    #pragma unroll
    for (int j = 0; j < 4; j++) qnr[j] = qn[q0 + j];

    float cmin[4] = {1e30f, 1e30f, 1e30f, 1e30f};
    float rmin[4];
    #pragma unroll
    for (int i = 0; i < 4; i++) {
        float rmn = 1e30f;
        #pragma unroll
        for (int j = 0; j < 4; j++) {
            float lo, hi;
            unpack2(lo, hi, acc[i][j]);
            float d2 = fmaxf(fmaf(-2.0f, lo + hi, pnr[i] + qnr[j]), 0.0f);
            rmn = fminf(rmn, d2);
            cmin[j] = fminf(cmin[j], d2 * ci2[i]);
        }
        rmin[i] = rmn;
    }

    // row mins: reduce over tx lanes (bits 0..3 of lane id)
    #pragma unroll
    for (int m = 1; m < 16; m <<= 1) {
        #pragma unroll
        for (int i = 0; i < 4; i++)
            rmin[i] = fminf(rmin[i], __shfl_xor_sync(0xFFFFFFFFu, rmin[i], m));
    }
    if (lane15 == 0 && (tid & 16)) {   // one writer per ty: lane 16 of each warp... 
        // (covered below by lane 0 writer; this branch intentionally empty)
    }
    if (lane15 == 0) {
        #pragma unroll
        for (int i = 0; i < 4; i++) rm[p0 + i] = rmin[i];
    }
    // col mins: reduce over ty bit inside warp (xor 16), then across warps via smem
    #pragma unroll
    for (int j = 0; j < 4; j++)
        cmin[j] = fminf(cmin[j], __shfl_xor_sync(0xFFFFFFFFu, cmin[j], 16));
    if (tid < (tid | 16)) {}           // no-op
    if ((tid & 16) == 0) {             // lanes 0..15 of each warp
        const int w = tid >> 5;
        #pragma unroll
        for (int j = 0; j < 4; j++) cm[w * CM_S + q0 + j] = cmin[j];
    }
    __syncthreads();

    // ---- Final: 128 sqrts + block sum ----
    float val = 0.0f;
    if (tid < NP) {
        val = conf[tid] * sqrtf(rm[tid]);
    } else if (tid < 2 * NP) {
        int q = tid - NP;
        float m = cm[q];
        #pragma unroll
        for (int w = 1; w < 8; w++) m = fminf(m, cm[w * CM_S + q]);
        val = sqrtf(m);
    }

    if (tid < 128) red[tid] = val;
    __syncthreads();
    if (tid < 64) red[tid] += red[tid + 64];
    __syncthreads();
    if (tid < 32) {
        float s = red[tid] + red[tid + 32];
        #pragma unroll
        for (int off = 16; off > 0; off >>= 1)
            s += __shfl_down_sync(0xFFFFFFFFu, s, off);
        if (tid == 0) out[bs] = s;
    }
}

extern "C" void kernel_launch(void* const* d_in, const int* in_sizes, int n_in,
                              void* d_out, int out_size)
{
    const float* inp = (const float*)d_in[0];
    const float* tgt = (const float*)d_in[1];
    float* out = (float*)d_out;
    cross_mse_loss_kernel<<<1024, 256>>>(inp, tgt, out);
}

// round 6
// speedup vs baseline: 1.1755x; 1.1032x over previous
#include <cuda_runtime.h>

// crossMSEloss: B=4, S=256, P=64, D=63
// out[b,s] = sum_p conf[p] * min_q ||pred_p - tgt_q||
//          + sum_q min_p ( ||pred_p - tgt_q|| / conf[p] )
//
// GEMM-form (norm trick), f32x2 FMA mainloop with 4p x 4q tiles (R3 layout).
// Targets scattered gmem -> st_t[d][q] directly with a per-row XOR chunk
// swizzle (conflict-light both on scatter-write and mainloop-read).
// pn folded into pred load; qn folded into target scatter. 3 syncthreads.

#define NP 64
#define SP_S 68     // preds stride: 272B
#define CM_S 68

typedef unsigned long long u64;

__device__ __forceinline__ void ffma2(u64& d, u64 a, u64 b) {
    asm("fma.rn.f32x2 %0, %1, %2, %0;" : "+l"(d) : "l"(a), "l"(b));
}
__device__ __forceinline__ void unpack2(float& lo, float& hi, u64 v) {
    asm("mov.b64 {%0, %1}, %2;" : "=f"(lo), "=f"(hi) : "l"(v));
}

// st_t physical float offset for logical (d, q):
//   row d (64 floats, 256B), 16B chunk (q>>2) XOR'd with (d&15), + (q&3)
__device__ __forceinline__ int stoff(int d, int q) {
    return d * 64 + 4 * ((q >> 2) ^ (d & 15)) + (q & 3);
}

__global__ __launch_bounds__(256, 4)
void cross_mse_loss_kernel(const float* __restrict__ inp,
                           const float* __restrict__ tgt,
                           float* __restrict__ out)
{
    __shared__ __align__(16) float sp[NP * SP_S];   // preds [p][d], d=63 -> 0
    __shared__ __align__(16) float st_t[NP * 64];   // targets [d][swizzled q]
    __shared__ float cm[8 * CM_S];                  // per-warp col-min partials
    __shared__ float rm[NP];
    __shared__ float conf[NP];
    __shared__ float cinv2[NP];
    __shared__ float pn[NP];
    __shared__ float qn[NP];
    __shared__ float red[128];

    const int bs   = blockIdx.x;
    const int tid  = threadIdx.x;
    const int lane = tid & 31;
    const int w    = tid >> 5;
    const int lane15 = tid & 15;

    const float* ip = inp + (size_t)bs * (NP * 64);
    const float* tp = tgt + (size_t)bs * (NP * 63);

    // ---- Preds (+conf) via float4; pn inline via 16-lane shuffle ----
    const float4* ip4 = (const float4*)ip;
    #pragma unroll
    for (int r = 0; r < 4; r++) {
        int idx = tid + r * 256;
        float4 v = ip4[idx];
        int p  = idx >> 4;
        int d4 = lane15 << 2;
        float* row = sp + p * SP_S + d4;
        float s;
        if (d4 == 60) {
            row[0] = v.x; row[1] = v.y; row[2] = v.z; row[3] = 0.0f;
            conf[p] = v.w;
            float ci = 1.0f / v.w;
            cinv2[p] = ci * ci;
            s = fmaf(v.x, v.x, fmaf(v.y, v.y, v.z * v.z));
        } else {
            row[0] = v.x; row[1] = v.y; row[2] = v.z; row[3] = v.w;
            s = fmaf(v.x, v.x, fmaf(v.y, v.y, fmaf(v.z, v.z, v.w * v.w)));
        }
        #pragma unroll
        for (int m = 1; m < 16; m <<= 1)
            s += __shfl_xor_sync(0xFFFFFFFFu, s, m);
        if (lane15 == 0) pn[p] = s;
    }

    // ---- Targets: each warp owns q = 8t + w; lane = d and d+32.
    //      Scatter into swizzled st_t and fold qn via warp reduction. ----
    #pragma unroll
    for (int t = 0; t < 8; t++) {
        const int q = t * 8 + w;
        const float* rowq = tp + q * 63;
        float v1 = rowq[lane];                                // d = lane (0..31)
        float v2 = (lane < 31) ? rowq[lane + 32] : 0.0f;      // d = lane+32 (32..62)
        st_t[stoff(lane, q)] = v1;
        if (lane < 31) st_t[stoff(lane + 32, q)] = v2;
        float s = fmaf(v1, v1, v2 * v2);
        #pragma unroll
        for (int m = 1; m < 32; m <<= 1)
            s += __shfl_xor_sync(0xFFFFFFFFu, s, m);
        if (lane == 0) qn[q] = s;
    }
    // d = 63 pad row
    if (tid < NP) st_t[63 * 64 + tid] = 0.0f;
    __syncthreads();

    // ---- Mainloop: 4p x 4q tiles, f32x2 packed along q-pairs? No: R3 form,
    //      f32x2 along q via 16B b-chunks (each ulonglong2 = 4 q-values). ----
    const int tx = lane15;           // q0 = 4*tx (logical chunk = tx)
    const int ty = tid >> 4;         // p0 = 4*ty
    const int q0 = tx * 4;
    const int p0 = ty * 4;

    u64 acc[4][4];   // acc[i][j2]: i = p-row, (j2) = q-pair {2j2, 2j2+1}... 
    // layout: acc[i][0],acc[i][1] <- chunk lo/hi pairs (q0+0/1, q0+2/3)
    #pragma unroll
    for (int i = 0; i < 4; i++)
        #pragma unroll
        for (int j = 0; j < 4; j++) acc[i][j] = 0ull;

    const float* a0 = sp + p0 * SP_S;

    #pragma unroll 4
    for (int dc = 0; dc < 64; dc += 4) {
        ulonglong2 b[4];
        #pragma unroll
        for (int d = 0; d < 4; d++) {
            const int dd = dc + d;
            b[d] = *(const ulonglong2*)(st_t + dd * 64 + ((tx ^ (dd & 15)) << 2));
        }
        #pragma unroll
        for (int i = 0; i < 4; i++) {
            float4 av = *(const float4*)(a0 + i * SP_S + dc);
            float a[4] = {av.x, av.y, av.z, av.w};
            #pragma unroll
            for (int d = 0; d < 4; d++) {
                u64 pa;
                asm("mov.b64 %0, {%1, %1};" : "=l"(pa) : "f"(a[d]));
                ffma2(acc[i][0], pa, b[d].x);    // q0+0, q0+1
                ffma2(acc[i][1], pa, b[d].y);    // q0+2, q0+3
                // acc[i][2], acc[i][3] unused in this scheme -- folded below
            }
        }
    }

    // ---- Epilogue ----
    float pnr[4], ci2[4], qnr[4];
    #pragma unroll
    for (int i = 0; i < 4; i++) { pnr[i] = pn[p0 + i]; ci2[i] = cinv2[p0 + i]; }
    #pragma unroll
    for (int j = 0; j < 4; j++) qnr[j] = qn[q0 + j];

    float cmin[4] = {1e30f, 1e30f, 1e30f, 1e30f};
    float rmin[4];
    #pragma unroll
    for (int i = 0; i < 4; i++) {
        float dot[4];
        unpack2(dot[0], dot[1], acc[i][0]);
        unpack2(dot[2], dot[3], acc[i][1]);
        float rmn = 1e30f;
        #pragma unroll
        for (int j = 0; j < 4; j++) {
            float d2 = fmaxf(fmaf(-2.0f, dot[j], pnr[i] + qnr[j]), 0.0f);
            rmn = fminf(rmn, d2);
            cmin[j] = fminf(cmin[j], d2 * ci2[i]);
        }
        rmin[i] = rmn;
    }

    // row mins: reduce over tx (lane bits 0..3)
    #pragma unroll
    for (int m = 1; m < 16; m <<= 1) {
        #pragma unroll
        for (int i = 0; i < 4; i++)
            rmin[i] = fminf(rmin[i], __shfl_xor_sync(0xFFFFFFFFu, rmin[i], m));
    }
    if (lane15 == 0) {
        #pragma unroll
        for (int i = 0; i < 4; i++) rm[p0 + i] = rmin[i];
    }
    // col mins: combine the two ty's in the warp, then across warps via cm
    #pragma unroll
    for (int j = 0; j < 4; j++)
        cmin[j] = fminf(cmin[j], __shfl_xor_sync(0xFFFFFFFFu, cmin[j], 16));
    if (lane < 16) {
        #pragma unroll
        for (int j = 0; j < 4; j++) cm[w * CM_S + q0 + j] = cmin[j];
    }
    __syncthreads();

    // ---- Final: 128 sqrts + block sum ----
    float val = 0.0f;
    if (tid < NP) {
        val = conf[tid] * sqrtf(rm[tid]);
    } else if (tid < 2 * NP) {
        int q = tid - NP;
        float m = cm[q];
        #pragma unroll
        for (int u = 1; u < 8; u++) m = fminf(m, cm[u * CM_S + q]);
        val = sqrtf(m);
    }

    if (tid < 128) red[tid] = val;
    __syncthreads();
    if (tid < 64) red[tid] += red[tid + 64];
    __syncthreads();
    if (tid < 32) {
        float s = red[tid] + red[tid + 32];
        #pragma unroll
        for (int off = 16; off > 0; off >>= 1)
            s += __shfl_down_sync(0xFFFFFFFFu, s, off);
        if (tid == 0) out[bs] = s;
    }
}

extern "C" void kernel_launch(void* const* d_in, const int* in_sizes, int n_in,
                              void* d_out, int out_size)
{
    const float* inp = (const float*)d_in[0];
    const float* tgt = (const float*)d_in[1];
    float* out = (float*)d_out;
    cross_mse_loss_kernel<<<1024, 256>>>(inp, tgt, out);
}